// round 8
// baseline (speedup 1.0000x reference)
#include <cuda_runtime.h>
#include <cstdint>

// LaneATT line NMS — Round 8 (R7 resubmit after infra failure; no functional
// change). Parallel fast path:
//  * P2d: local-memory cnt[] (dynamic-index LDL/STL) replaced by parallel
//    first-exhaustion precompute -> scalar walk is pure shared/register
//  * P2c: 4 pairs per warp batched; interleaved butterfly reductions (ILP)
//  * P1:  no keys[] stores (64KB crossbar saved); lane holds 8 consecutive
//    scores via 2x LDG.128; top-4 scans are register-only
//  * P2a: rank-count via LDS.128 (64 iters)
// Fallback (cold, exact) rebuilds keys[] from scores, zeroes consumed, and
// runs the proven block-cooperative greedy loop. Non-fast-path shapes
// (chunk > 256 or n % 8 != 0) go straight to fallback.

#define N_OFFSETS 72
#define N_STRIPS 71
#define PROP_COLS 77
#define MAXK 16
#define M 16
#define NPAIRS (M * (M - 1) / 2)   // 120
#define NT 1024
#define NWARPS 32
#define TOPT 4
#define FULL 0xFFFFFFFFu

__device__ __forceinline__ uint64_t warp_max_u64(uint64_t v) {
    uint32_t hi = (uint32_t)(v >> 32), lo = (uint32_t)v;
    uint32_t mhi = __reduce_max_sync(FULL, hi);
    uint32_t lo2 = (hi == mhi) ? lo : 0u;
    uint32_t mlo = __reduce_max_sync(FULL, lo2);
    return ((uint64_t)mhi << 32) | mlo;
}

__device__ __forceinline__ uint64_t make_key(float sc, int idx) {
    uint32_t b = __float_as_uint(sc);
    b = (b & 0x80000000u) ? ~b : (b | 0x80000000u);
    return ((uint64_t)b << 32) | (FULL - (uint32_t)idx);
}

__global__ __launch_bounds__(NT, 1)
void laneatt_nms_kernel(const float* __restrict__ proposals,
                        const float* __restrict__ scores,
                        const int* __restrict__ thres_ptr,
                        const int* __restrict__ topk_ptr,
                        float* __restrict__ out,
                        int out_size, int n)
{
    extern __shared__ uint64_t keys[];                 // fallback only

    __shared__ __align__(16) uint64_t toplist[NWARPS * TOPT];
    __shared__ uint64_t L[M];
    __shared__ int      Lgi[M], Lcs[M], Lce[M];
    __shared__ __align__(16) float cxs[M][80];
    __shared__ uint32_t Smask[M];
    __shared__ int      kept_gi[MAXK], kept_slot[MAXK];
    __shared__ int      sh_kc, sh_consumed, sh_fb, sh_fe;
    // fallback-only
    __shared__ float    kept_xs[MAXK][N_OFFSETS];
    __shared__ int      kept_s[MAXK], kept_e[MAXK];
    __shared__ uint64_t wmax_sh[NWARPS];
    __shared__ uint64_t sh_win;
    __shared__ float    cand2[N_OFFSETS];
    __shared__ int      sh_cs2, sh_ce2, supp[MAXK], sh_accept;

    const int tid  = threadIdx.x;
    const int warp = tid >> 5;
    const int lane = tid & 31;
    const int cs   = (n + NWARPS - 1) / NWARPS;
    const bool fastshape = (cs <= 8 * 32) && (n % 8 == 0);

    // ---- scalar params (robust to int32 or float32 bit encoding) ----
    int tv = *thres_ptr;
    float thr = (tv >= 0 && tv < 1000000) ? (float)tv : __int_as_float(tv);
    int tk = *topk_ptr;
    if (tk <= 0 || tk > 100000) tk = (int)__int_as_float(tk);
    if (tk > MAXK) tk = MAXK;

    if (tid < M) { L[tid] = 0; Smask[tid] = 0; Lgi[tid] = -1; }
    if (tid == 0) { sh_fe = M; sh_fb = 0; sh_kc = 0; sh_consumed = 0; }

    if (fastshape) {
        // ============ P1: register keys + per-chunk sorted top-4 =======
        {
            const int c = warp;
            const int lo = c * cs;
            const int base = lo + lane * 8;            // 8 consecutive
            uint64_t vals[8];
            if (base + 7 < n) {
                float4 s0 = *(const float4*)(scores + base);
                float4 s1 = *(const float4*)(scores + base + 4);
                vals[0] = make_key(s0.x, base + 0);
                vals[1] = make_key(s0.y, base + 1);
                vals[2] = make_key(s0.z, base + 2);
                vals[3] = make_key(s0.w, base + 3);
                vals[4] = make_key(s1.x, base + 4);
                vals[5] = make_key(s1.y, base + 5);
                vals[6] = make_key(s1.z, base + 6);
                vals[7] = make_key(s1.w, base + 7);
            } else {
                #pragma unroll
                for (int q = 0; q < 8; ++q)
                    vals[q] = (base + q < n) ? make_key(scores[base + q], base + q) : 0;
            }
            uint64_t prev = 0xFFFFFFFFFFFFFFFFull;
            int t = 0;
            for (; t < TOPT; ++t) {
                uint64_t m = 0;
                #pragma unroll
                for (int q = 0; q < 8; ++q) {
                    uint64_t u = vals[q];
                    if (u < prev && u > m) m = u;
                }
                uint64_t wm = warp_max_u64(m);
                if (lane == 0) toplist[c * TOPT + t] = wm;
                if (wm == 0) break;
                prev = wm;
            }
            for (; t < TOPT; ++t) if (lane == 0) toplist[c * TOPT + t] = 0;
        }
        __syncthreads();

        // ============ P2a: rank-count merge (LDS.128) ==================
        if (tid < NWARPS * TOPT) {
            uint64_t key = toplist[tid];
            if (key) {
                int r = 0;
                const ulonglong2* t2 = (const ulonglong2*)toplist;
                #pragma unroll 8
                for (int q = 0; q < NWARPS * TOPT / 2; ++q) {
                    ulonglong2 v = t2[q];
                    r += (v.x > key) + (v.y > key);
                }
                if (r < M) L[r] = key;
            }
        }
        __syncthreads();

        // ============ P2b: parallel candidate prep =====================
        if (warp < M) {
            uint64_t k = L[warp];
            int gi = k ? (int)(FULL - (uint32_t)k) : -1;
            if (lane == 0) Lgi[warp] = gi;
            if (gi >= 0) {
                const float* row = proposals + (size_t)gi * PROP_COLS;
                #pragma unroll
                for (int t = 0; t < 3; ++t) {
                    int q = lane + t * 32;
                    if (q < N_OFFSETS) cxs[warp][q] = row[5 + q];
                }
                if (lane == 0) {
                    int s = (int)rintf(row[2] * (float)N_STRIPS);  // half-even
                    int e = min(s + (int)rintf(row[4]) - 1, N_STRIPS);
                    Lcs[warp] = s; Lce[warp] = e;
                }
            }
        }
        __syncthreads();

        // ---- first-exhaustion precompute (parallel, replaces local cnt[])
        if (tid < M && Lgi[tid] >= 0) {
            int c = Lgi[tid] / cs, cnt = 0;
            for (int j = 0; j <= tid; ++j)
                if (Lgi[j] >= 0 && Lgi[j] / cs == c) ++cnt;
            if (cnt >= TOPT) atomicMin(&sh_fe, tid);
        }

        // ============ P2c: symmetric matrix, 4 batched pairs/warp ======
        {
            float dd[4]; int pps[4], ppe[4];
            #pragma unroll
            for (int r = 0; r < 4; ++r) {
                int p = warp + r * NWARPS;
                int i = 0, pp = p, j = 0;
                bool a = (p < NPAIRS);
                if (a) {
                    while (pp >= M - 1 - i) { pp -= (M - 1 - i); ++i; }
                    j = i + 1 + pp;
                    a = (Lgi[i] >= 0) && (Lgi[j] >= 0);
                }
                float d = 0.0f; int ps = 1, pe = 0;
                if (a) {
                    ps = max(Lcs[i], Lcs[j]);
                    pe = min(Lce[i], Lce[j]);
                    #pragma unroll
                    for (int t = 0; t < 3; ++t) {
                        int k = lane + t * 32;
                        if (k < N_OFFSETS && k >= ps && k <= pe)
                            d += fabsf(cxs[i][k] - cxs[j][k]);
                    }
                }
                dd[r] = d; pps[r] = ps; ppe[r] = pe;
            }
            #pragma unroll
            for (int o = 16; o > 0; o >>= 1) {      // 4 interleaved chains
                dd[0] += __shfl_xor_sync(FULL, dd[0], o);
                dd[1] += __shfl_xor_sync(FULL, dd[1], o);
                dd[2] += __shfl_xor_sync(FULL, dd[2], o);
                dd[3] += __shfl_xor_sync(FULL, dd[3], o);
            }
            if (lane == 0) {
                #pragma unroll
                for (int r = 0; r < 4; ++r) {
                    int p = warp + r * NWARPS;
                    if (p >= NPAIRS || ppe[r] < pps[r]) continue;
                    float cnt = (float)max(ppe[r] - pps[r] + 1, 1);
                    if (dd[r] / cnt < thr) {
                        int i = 0, pp = p;
                        while (pp >= M - 1 - i) { pp -= (M - 1 - i); ++i; }
                        int j = i + 1 + pp;
                        atomicOr(&Smask[i], 1u << j);
                        atomicOr(&Smask[j], 1u << i);
                    }
                }
            }
        }
        __syncthreads();

        // ============ P2d: scalar greedy walk (shared/regs only) =======
        if (tid == 0) {
            uint32_t removed = 0;
            int kc = 0, consumed = 0, fb = 0;
            int fe = sh_fe;
            for (int i = 0; i < M; ++i) {
                if (kc >= tk) break;
                int gi = Lgi[i];
                if (gi < 0) break;                  // pool exhausted (exact)
                if (i > fe) { fb = 1; break; }      // chunk top-4 used up
                consumed = i + 1;
                if (!((removed >> i) & 1u)) {
                    kept_gi[kc] = gi; kept_slot[kc] = i; ++kc;
                    removed |= Smask[i];
                }
            }
            if (kc < tk) fb = 1;  // continue exactly (no-op if truly empty)
            sh_kc = kc; sh_consumed = consumed; sh_fb = fb;
        }
    } else {
        if (tid == 0) sh_fb = 1;   // generic shape: exact slow path
    }
    __syncthreads();

    // ================= Fallback (cold, exact) ==========================
    if (sh_fb) {
        // rebuild keys from scores, zero consumed, seed kept arrays
        for (int i = tid; i < n; i += NT) keys[i] = make_key(scores[i], i);
        __syncthreads();
        for (int t = tid; t < sh_consumed; t += NT) keys[Lgi[t]] = 0;
        for (int j = warp; j < sh_kc; j += NWARPS) {
            int sl = kept_slot[j];
            #pragma unroll
            for (int t = 0; t < 3; ++t) {
                int q = lane + t * 32;
                if (q < N_OFFSETS) kept_xs[j][q] = cxs[sl][q];
            }
            if (lane == 0) { kept_s[j] = Lcs[sl]; kept_e[j] = Lce[sl]; }
        }
        __syncthreads();

        int kc = sh_kc;
        for (int it = 0; it < n && kc < tk; ++it) {
            uint64_t m = 0;
            for (int i = tid; i < n; i += NT) {
                uint64_t v = keys[i];
                if (v > m) m = v;
            }
            m = warp_max_u64(m);
            if (lane == 0) wmax_sh[warp] = m;
            __syncthreads();
            if (warp == 0) {
                uint64_t v = wmax_sh[lane];
                v = warp_max_u64(v);
                if (lane == 0) sh_win = v;
            }
            __syncthreads();
            uint64_t win = sh_win;
            if (win == 0) break;
            int gi = (int)(FULL - (uint32_t)win);
            const float* row = proposals + (size_t)gi * PROP_COLS;
            if (tid < N_OFFSETS) cand2[tid] = row[5 + tid];
            if (tid == 0) {
                keys[gi] = 0;
                int s = (int)rintf(row[2] * (float)N_STRIPS);
                int e = min(s + (int)rintf(row[4]) - 1, N_STRIPS);
                sh_cs2 = s; sh_ce2 = e;
            }
            __syncthreads();
            if (warp < kc) {
                int ps = max(sh_cs2, kept_s[warp]);
                int pe = min(sh_ce2, kept_e[warp]);
                float d = 0.0f;
                #pragma unroll
                for (int t = 0; t < 3; ++t) {
                    int off = lane + t * 32;
                    if (off < N_OFFSETS && off >= ps && off <= pe)
                        d += fabsf(cand2[off] - kept_xs[warp][off]);
                }
                #pragma unroll
                for (int o = 16; o > 0; o >>= 1)
                    d += __shfl_xor_sync(FULL, d, o);
                if (lane == 0) {
                    float cnt2 = (float)max(pe - ps + 1, 1);
                    supp[warp] = (pe >= ps) && (d / cnt2 < thr);
                }
            }
            __syncthreads();
            if (tid == 0) {
                int s = 0;
                for (int j = 0; j < kc; ++j) s |= supp[j];
                sh_accept = !s;
            }
            __syncthreads();
            if (sh_accept) {                         // uniform
                if (tid < N_OFFSETS) kept_xs[kc][tid] = cand2[tid];
                if (tid == 0) { kept_s[kc] = sh_cs2; kept_e[kc] = sh_ce2;
                                kept_gi[kc] = gi; }
                __syncthreads();
                ++kc;
            }
        }
        if (tid == 0) sh_kc = kc;
        __syncthreads();
    }

    // ================= Output ==========================================
    // tk rows of 78 (77 proposal cols + score), zero-padded, then num_kept
    int kc = sh_kc;
    int row_elems = tk * (PROP_COLS + 1);
    for (int idx = tid; idx < out_size; idx += NT) {
        float v = 0.0f;
        if (idx < row_elems) {
            int r = idx / (PROP_COLS + 1);
            int c = idx - r * (PROP_COLS + 1);
            if (r < kc) {
                int gi = kept_gi[r];
                v = (c < PROP_COLS) ? proposals[(size_t)gi * PROP_COLS + c]
                                    : scores[gi];
            }
        } else if (idx == row_elems) {
            v = (float)kc;
        }
        out[idx] = v;
    }
}

extern "C" void kernel_launch(void* const* d_in, const int* in_sizes, int n_in,
                              void* d_out, int out_size) {
    const float* proposals = (const float*)d_in[0];
    const float* scores    = (const float*)d_in[1];
    const int*   thres     = (const int*)d_in[2];
    const int*   topk      = (const int*)d_in[3];
    float* out = (float*)d_out;

    int n = in_sizes[1];
    size_t smem = (size_t)n * sizeof(uint64_t);   // fallback keys

    static bool attr_set = false;                 // idempotent attribute only
    if (!attr_set) {
        cudaFuncSetAttribute(laneatt_nms_kernel,
                             cudaFuncAttributeMaxDynamicSharedMemorySize,
                             (int)smem);
        attr_set = true;
    }

    laneatt_nms_kernel<<<1, NT, smem>>>(proposals, scores, thres, topk,
                                        out, out_size, n);
}

// round 9
// speedup vs baseline: 1.0129x; 1.0129x over previous
#include <cuda_runtime.h>
#include <cstdint>

// LaneATT line NMS — Round 9. R6/R8 parallel fast path, with the THIRD
// dependent global-load epoch removed: P2b now stages the candidate's full
// 77-col proposal row AND its score in shared (same load epoch), so the
// fast-path output phase is served entirely from shared memory. Calibration
// from R8: this idle-clock single-CTA kernel runs ~350-500MHz; only serial
// dependency-chain cuts (LDG epochs, REDUX chains) move the needle.
//
// Fast path: P1 per-chunk sorted top-4 (register scans, no keys[] traffic)
// -> P2a rank-count merge -> P2b full-row stage -> P2c symmetric 16x16
// suppression matrix -> P2d scalar bitmask walk. Exactness guards fall back
// to the proven block-cooperative loop (cold), which rebuilds keys[].

#define N_OFFSETS 72
#define N_STRIPS 71
#define PROP_COLS 77
#define MAXK 16
#define M 16
#define NPAIRS (M * (M - 1) / 2)   // 120
#define NT 1024
#define NWARPS 32
#define TOPT 4
#define FULL 0xFFFFFFFFu

__device__ __forceinline__ uint64_t warp_max_u64(uint64_t v) {
    uint32_t hi = (uint32_t)(v >> 32), lo = (uint32_t)v;
    uint32_t mhi = __reduce_max_sync(FULL, hi);
    uint32_t lo2 = (hi == mhi) ? lo : 0u;
    uint32_t mlo = __reduce_max_sync(FULL, lo2);
    return ((uint64_t)mhi << 32) | mlo;
}

__device__ __forceinline__ uint64_t make_key(float sc, int idx) {
    uint32_t b = __float_as_uint(sc);
    b = (b & 0x80000000u) ? ~b : (b | 0x80000000u);
    return ((uint64_t)b << 32) | (FULL - (uint32_t)idx);
}

__global__ __launch_bounds__(NT, 1)
void laneatt_nms_kernel(const float* __restrict__ proposals,
                        const float* __restrict__ scores,
                        const int* __restrict__ thres_ptr,
                        const int* __restrict__ topk_ptr,
                        float* __restrict__ out,
                        int out_size, int n)
{
    extern __shared__ uint64_t keys[];                 // fallback only

    __shared__ __align__(16) uint64_t toplist[NWARPS * TOPT];
    __shared__ uint64_t L[M];
    __shared__ int      Lgi[M], Lcs[M], Lce[M];
    __shared__ __align__(16) float crow[M][80];        // [0..76]=row, [77]=score
    __shared__ uint32_t Smask[M];
    __shared__ int      kept_gi[MAXK], kept_slot[MAXK];
    __shared__ int      sh_kc, sh_consumed, sh_fb, sh_fe;
    // fallback-only
    __shared__ float    kept_xs[MAXK][N_OFFSETS];
    __shared__ int      kept_s[MAXK], kept_e[MAXK];
    __shared__ uint64_t wmax_sh[NWARPS];
    __shared__ uint64_t sh_win;
    __shared__ float    cand2[N_OFFSETS];
    __shared__ int      sh_cs2, sh_ce2, supp[MAXK], sh_accept;

    const int tid  = threadIdx.x;
    const int warp = tid >> 5;
    const int lane = tid & 31;
    const int cs   = (n + NWARPS - 1) / NWARPS;
    const bool fastshape = (cs <= 8 * 32) && (n % 8 == 0);

    // ---- scalar params (robust to int32 or float32 bit encoding) ----
    int tv = *thres_ptr;
    float thr = (tv >= 0 && tv < 1000000) ? (float)tv : __int_as_float(tv);
    int tk = *topk_ptr;
    if (tk <= 0 || tk > 100000) tk = (int)__int_as_float(tk);
    if (tk > MAXK) tk = MAXK;

    if (tid < M) { L[tid] = 0; Smask[tid] = 0; Lgi[tid] = -1; }
    if (tid == 0) { sh_fe = M; sh_fb = 0; sh_kc = 0; sh_consumed = 0; }

    if (fastshape) {
        // ============ P1: register keys + per-chunk sorted top-4 =======
        {
            const int c = warp;
            const int base = c * cs + lane * 8;        // 8 consecutive
            uint64_t vals[8];
            if (base + 7 < n) {
                float4 s0 = *(const float4*)(scores + base);
                float4 s1 = *(const float4*)(scores + base + 4);
                vals[0] = make_key(s0.x, base + 0);
                vals[1] = make_key(s0.y, base + 1);
                vals[2] = make_key(s0.z, base + 2);
                vals[3] = make_key(s0.w, base + 3);
                vals[4] = make_key(s1.x, base + 4);
                vals[5] = make_key(s1.y, base + 5);
                vals[6] = make_key(s1.z, base + 6);
                vals[7] = make_key(s1.w, base + 7);
            } else {
                #pragma unroll
                for (int q = 0; q < 8; ++q)
                    vals[q] = (base + q < n) ? make_key(scores[base + q], base + q) : 0;
            }
            uint64_t prev = 0xFFFFFFFFFFFFFFFFull;
            int t = 0;
            for (; t < TOPT; ++t) {
                uint64_t m = 0;
                #pragma unroll
                for (int q = 0; q < 8; ++q) {
                    uint64_t u = vals[q];
                    if (u < prev && u > m) m = u;
                }
                uint64_t wm = warp_max_u64(m);
                if (lane == 0) toplist[c * TOPT + t] = wm;
                if (wm == 0) break;
                prev = wm;
            }
            for (; t < TOPT; ++t) if (lane == 0) toplist[c * TOPT + t] = 0;
        }
        __syncthreads();

        // ============ P2a: rank-count merge (LDS.128) ==================
        if (tid < NWARPS * TOPT) {
            uint64_t key = toplist[tid];
            if (key) {
                int r = 0;
                const ulonglong2* t2 = (const ulonglong2*)toplist;
                #pragma unroll 8
                for (int q = 0; q < NWARPS * TOPT / 2; ++q) {
                    ulonglong2 v = t2[q];
                    r += (v.x > key) + (v.y > key);
                }
                if (r < M) L[r] = key;
            }
        }
        __syncthreads();

        // ============ P2b: stage FULL row + score in shared ============
        if (warp < M) {
            uint64_t k = L[warp];
            int gi = k ? (int)(FULL - (uint32_t)k) : -1;
            if (lane == 0) Lgi[warp] = gi;
            if (gi >= 0) {
                const float* row = proposals + (size_t)gi * PROP_COLS;
                #pragma unroll
                for (int t = 0; t < 3; ++t) {
                    int q = lane + t * 32;
                    if (q < PROP_COLS) crow[warp][q] = row[q];
                }
                if (lane == 0) {
                    crow[warp][PROP_COLS] = scores[gi];        // same epoch
                    int s = (int)rintf(row[2] * (float)N_STRIPS);  // half-even
                    int e = min(s + (int)rintf(row[4]) - 1, N_STRIPS);
                    Lcs[warp] = s; Lce[warp] = e;
                }
            }
        }
        __syncthreads();

        // ---- first-exhaustion precompute (parallel) ----
        if (tid < M && Lgi[tid] >= 0) {
            int c = Lgi[tid] / cs, cnt = 0;
            for (int j = 0; j <= tid; ++j)
                if (Lgi[j] >= 0 && Lgi[j] / cs == c) ++cnt;
            if (cnt >= TOPT) atomicMin(&sh_fe, tid);
        }

        // ============ P2c: symmetric matrix, 4 batched pairs/warp ======
        {
            float dd[4]; int pps[4], ppe[4];
            #pragma unroll
            for (int r = 0; r < 4; ++r) {
                int p = warp + r * NWARPS;
                int i = 0, pp = p, j = 0;
                bool a = (p < NPAIRS);
                if (a) {
                    while (pp >= M - 1 - i) { pp -= (M - 1 - i); ++i; }
                    j = i + 1 + pp;
                    a = (Lgi[i] >= 0) && (Lgi[j] >= 0);
                }
                float d = 0.0f; int ps = 1, pe = 0;
                if (a) {
                    ps = max(Lcs[i], Lcs[j]);
                    pe = min(Lce[i], Lce[j]);
                    #pragma unroll
                    for (int t = 0; t < 3; ++t) {
                        int k = lane + t * 32;
                        if (k < N_OFFSETS && k >= ps && k <= pe)
                            d += fabsf(crow[i][5 + k] - crow[j][5 + k]);
                    }
                }
                dd[r] = d; pps[r] = ps; ppe[r] = pe;
            }
            #pragma unroll
            for (int o = 16; o > 0; o >>= 1) {      // 4 interleaved chains
                dd[0] += __shfl_xor_sync(FULL, dd[0], o);
                dd[1] += __shfl_xor_sync(FULL, dd[1], o);
                dd[2] += __shfl_xor_sync(FULL, dd[2], o);
                dd[3] += __shfl_xor_sync(FULL, dd[3], o);
            }
            if (lane == 0) {
                #pragma unroll
                for (int r = 0; r < 4; ++r) {
                    int p = warp + r * NWARPS;
                    if (p >= NPAIRS || ppe[r] < pps[r]) continue;
                    float cnt = (float)max(ppe[r] - pps[r] + 1, 1);
                    if (dd[r] / cnt < thr) {
                        int i = 0, pp = p;
                        while (pp >= M - 1 - i) { pp -= (M - 1 - i); ++i; }
                        int j = i + 1 + pp;
                        atomicOr(&Smask[i], 1u << j);
                        atomicOr(&Smask[j], 1u << i);
                    }
                }
            }
        }
        __syncthreads();

        // ============ P2d: scalar greedy walk ==========================
        if (tid == 0) {
            uint32_t removed = 0;
            int kc = 0, consumed = 0, fb = 0;
            int fe = sh_fe;
            for (int i = 0; i < M; ++i) {
                if (kc >= tk) break;
                int gi = Lgi[i];
                if (gi < 0) break;                  // pool exhausted (exact)
                if (i > fe) { fb = 1; break; }      // chunk top-4 used up
                consumed = i + 1;
                if (!((removed >> i) & 1u)) {
                    kept_gi[kc] = gi; kept_slot[kc] = i; ++kc;
                    removed |= Smask[i];
                }
            }
            if (kc < tk) fb = 1;  // continue exactly (no-op if truly empty)
            sh_kc = kc; sh_consumed = consumed; sh_fb = fb;
        }
    } else {
        if (tid == 0) sh_fb = 1;   // generic shape: exact slow path
    }
    __syncthreads();

    // ================= Fallback (cold, exact) ==========================
    if (sh_fb) {
        for (int i = tid; i < n; i += NT) keys[i] = make_key(scores[i], i);
        __syncthreads();
        for (int t = tid; t < sh_consumed; t += NT) keys[Lgi[t]] = 0;
        for (int j = warp; j < sh_kc; j += NWARPS) {
            int sl = kept_slot[j];
            #pragma unroll
            for (int t = 0; t < 3; ++t) {
                int q = lane + t * 32;
                if (q < N_OFFSETS) kept_xs[j][q] = crow[sl][5 + q];
            }
            if (lane == 0) { kept_s[j] = Lcs[sl]; kept_e[j] = Lce[sl]; }
        }
        __syncthreads();

        int kc = sh_kc;
        for (int it = 0; it < n && kc < tk; ++it) {
            uint64_t m = 0;
            for (int i = tid; i < n; i += NT) {
                uint64_t v = keys[i];
                if (v > m) m = v;
            }
            m = warp_max_u64(m);
            if (lane == 0) wmax_sh[warp] = m;
            __syncthreads();
            if (warp == 0) {
                uint64_t v = wmax_sh[lane];
                v = warp_max_u64(v);
                if (lane == 0) sh_win = v;
            }
            __syncthreads();
            uint64_t win = sh_win;
            if (win == 0) break;
            int gi = (int)(FULL - (uint32_t)win);
            const float* row = proposals + (size_t)gi * PROP_COLS;
            if (tid < N_OFFSETS) cand2[tid] = row[5 + tid];
            if (tid == 0) {
                keys[gi] = 0;
                int s = (int)rintf(row[2] * (float)N_STRIPS);
                int e = min(s + (int)rintf(row[4]) - 1, N_STRIPS);
                sh_cs2 = s; sh_ce2 = e;
            }
            __syncthreads();
            if (warp < kc) {
                int ps = max(sh_cs2, kept_s[warp]);
                int pe = min(sh_ce2, kept_e[warp]);
                float d = 0.0f;
                #pragma unroll
                for (int t = 0; t < 3; ++t) {
                    int off = lane + t * 32;
                    if (off < N_OFFSETS && off >= ps && off <= pe)
                        d += fabsf(cand2[off] - kept_xs[warp][off]);
                }
                #pragma unroll
                for (int o = 16; o > 0; o >>= 1)
                    d += __shfl_xor_sync(FULL, d, o);
                if (lane == 0) {
                    float cnt2 = (float)max(pe - ps + 1, 1);
                    supp[warp] = (pe >= ps) && (d / cnt2 < thr);
                }
            }
            __syncthreads();
            if (tid == 0) {
                int s = 0;
                for (int j = 0; j < kc; ++j) s |= supp[j];
                sh_accept = !s;
            }
            __syncthreads();
            if (sh_accept) {                         // uniform
                if (tid < N_OFFSETS) kept_xs[kc][tid] = cand2[tid];
                if (tid == 0) { kept_s[kc] = sh_cs2; kept_e[kc] = sh_ce2;
                                kept_gi[kc] = gi; }
                __syncthreads();
                ++kc;
            }
        }
        if (tid == 0) sh_kc = kc;
        __syncthreads();
    }

    // ================= Output ==========================================
    // tk rows of 78 (77 proposal cols + score), zero-padded, then num_kept.
    // Fast path: pure shared (crow). Fallback: global gather (cold).
    int kc = sh_kc;
    int fb = sh_fb;
    int row_elems = tk * (PROP_COLS + 1);
    for (int idx = tid; idx < out_size; idx += NT) {
        float v = 0.0f;
        if (idx < row_elems) {
            int r = idx / (PROP_COLS + 1);
            int c = idx - r * (PROP_COLS + 1);
            if (r < kc) {
                if (!fb) {
                    v = crow[kept_slot[r]][c];       // [77] holds the score
                } else {
                    int gi = kept_gi[r];
                    v = (c < PROP_COLS) ? proposals[(size_t)gi * PROP_COLS + c]
                                        : scores[gi];
                }
            }
        } else if (idx == row_elems) {
            v = (float)kc;
        }
        out[idx] = v;
    }
}

extern "C" void kernel_launch(void* const* d_in, const int* in_sizes, int n_in,
                              void* d_out, int out_size) {
    const float* proposals = (const float*)d_in[0];
    const float* scores    = (const float*)d_in[1];
    const int*   thres     = (const int*)d_in[2];
    const int*   topk      = (const int*)d_in[3];
    float* out = (float*)d_out;

    int n = in_sizes[1];
    size_t smem = (size_t)n * sizeof(uint64_t);   // fallback keys

    static bool attr_set = false;                 // idempotent attribute only
    if (!attr_set) {
        cudaFuncSetAttribute(laneatt_nms_kernel,
                             cudaFuncAttributeMaxDynamicSharedMemorySize,
                             (int)smem);
        attr_set = true;
    }

    laneatt_nms_kernel<<<1, NT, smem>>>(proposals, scores, thres, topk,
                                        out, out_size, n);
}